// round 1
// baseline (speedup 1.0000x reference)
#include <cuda_runtime.h>

// Problem constants
#define B_   8
#define T_   2048
#define C_   1024
#define H_   64
#define NROW (B_ * T_)        // 16384
#define PAD  65               // 64 + 1 padding for bank-conflict-free smem

// Scratch for q,k,v projections (allocation-free rule: device globals)
__device__ float g_q[NROW * H_];
__device__ float g_k[NROW * H_];
__device__ float g_v[NROW * H_];

// ---------------------------------------------------------------------------
// Kernel 1: fused QKV projection.
// Each block: 64 rows of x  ×  192 combined output cols (q|k|v).
// 256 threads as 16x16; thread owns rows {ty+16i}, cols {tx+16j}, 4x12 accum.
// ---------------------------------------------------------------------------
__global__ __launch_bounds__(256) void qkv_proj(
    const float* __restrict__ x,
    const float* __restrict__ Wk,
    const float* __restrict__ Wq,
    const float* __restrict__ Wv)
{
    __shared__ float xs[64][33];    // 64 rows x 32 k, padded
    __shared__ float ws[32][193];   // 32 k x 192 cols, padded

    const int tid = threadIdx.x;
    const int ty = tid >> 4;
    const int tx = tid & 15;
    const long rowBase = (long)blockIdx.x * 64;

    float acc[4][12];
#pragma unroll
    for (int i = 0; i < 4; i++)
#pragma unroll
        for (int j = 0; j < 12; j++) acc[i][j] = 0.0f;

    for (int kt = 0; kt < C_; kt += 32) {
        // load x tile: 64x32
#pragma unroll
        for (int idx = tid; idx < 64 * 32; idx += 256) {
            int r  = idx >> 5;
            int kk = idx & 31;
            xs[r][kk] = x[(rowBase + r) * C_ + kt + kk];
        }
        // load combined W tile: 32x192  (cols 0-63: Wq, 64-127: Wk, 128-191: Wv)
#pragma unroll
        for (int idx = tid; idx < 32 * 192; idx += 256) {
            int kk = idx / 192;
            int c  = idx - kk * 192;
            const float* W = (c < 64) ? Wq : ((c < 128) ? Wk : Wv);
            int cc = c & 63;
            ws[kk][c] = W[(kt + kk) * H_ + cc];
        }
        __syncthreads();

#pragma unroll
        for (int kk = 0; kk < 32; kk++) {
            float a[4], b[12];
#pragma unroll
            for (int i = 0; i < 4; i++) a[i] = xs[ty + 16 * i][kk];
#pragma unroll
            for (int j = 0; j < 12; j++) b[j] = ws[kk][tx + 16 * j];
#pragma unroll
            for (int i = 0; i < 4; i++)
#pragma unroll
                for (int j = 0; j < 12; j++) acc[i][j] = fmaf(a[i], b[j], acc[i][j]);
        }
        __syncthreads();
    }

    // write out: j 0-3 -> q, 4-7 -> k, 8-11 -> v
#pragma unroll
    for (int i = 0; i < 4; i++) {
        long r = rowBase + ty + 16 * i;
#pragma unroll
        for (int j = 0; j < 12; j++) {
            int c = tx + 16 * j;
            if (c < 64)       g_q[r * H_ + c]         = acc[i][j];
            else if (c < 128) g_k[r * H_ + (c - 64)]  = acc[i][j];
            else              g_v[r * H_ + (c - 128)] = acc[i][j];
        }
    }
}

// ---------------------------------------------------------------------------
// Kernel 2: causal flash attention over g_q/g_k/g_v.
// Block = 256 threads, one 64-row Q tile per block, loop over 64-key tiles
// kt = 0..qt. Online softmax, 4x4 register fragments, smem-staged P.
// grid = (32 q-tiles, 8 batches); heavy tiles launched first (reverse map).
// ---------------------------------------------------------------------------
__global__ __launch_bounds__(256) void flash_attn(float* __restrict__ out)
{
    extern __shared__ float sm[];
    float* Qs = sm;                 // [64][PAD]
    float* Ks = sm + 64 * PAD;
    float* Vs = sm + 2 * 64 * PAD;
    float* Ps = sm + 3 * 64 * PAD;

    const int b  = blockIdx.y;
    const int qt = (gridDim.x - 1) - blockIdx.x;   // heavy (late) tiles first
    const int tid = threadIdx.x;
    const int ty = tid >> 4;
    const int tx = tid & 15;

    const float scale = 0.03125f;  // C^-0.5 = 1/32

    // Load Q tile
    const float* qptr = g_q + ((long)b * T_ + (long)qt * 64) * H_;
#pragma unroll
    for (int idx = tid; idx < 64 * 64; idx += 256) {
        int r = idx >> 6, c = idx & 63;
        Qs[r * PAD + c] = qptr[r * 64 + c];
    }

    float m[4], l[4], O[4][4];
#pragma unroll
    for (int i = 0; i < 4; i++) {
        m[i] = -1e30f; l[i] = 0.0f;
#pragma unroll
        for (int j = 0; j < 4; j++) O[i][j] = 0.0f;
    }

    for (int kt = 0; kt <= qt; kt++) {
        __syncthreads();   // previous PV reads of Ks/Vs done; Q load done (iter 0)

        const float* kptr = g_k + ((long)b * T_ + (long)kt * 64) * H_;
        const float* vptr = g_v + ((long)b * T_ + (long)kt * 64) * H_;
#pragma unroll
        for (int idx = tid; idx < 64 * 64; idx += 256) {
            int r = idx >> 6, c = idx & 63;
            Ks[r * PAD + c] = kptr[r * 64 + c];
            Vs[r * PAD + c] = vptr[r * 64 + c];
        }
        __syncthreads();

        // S = Q @ K^T  (4x4 fragment per thread)
        float S[4][4];
#pragma unroll
        for (int i = 0; i < 4; i++)
#pragma unroll
            for (int j = 0; j < 4; j++) S[i][j] = 0.0f;

#pragma unroll 8
        for (int h = 0; h < 64; h++) {
            float a[4], bb[4];
#pragma unroll
            for (int i = 0; i < 4; i++) a[i]  = Qs[(ty + 16 * i) * PAD + h];
#pragma unroll
            for (int j = 0; j < 4; j++) bb[j] = Ks[(tx + 16 * j) * PAD + h];
#pragma unroll
            for (int i = 0; i < 4; i++)
#pragma unroll
                for (int j = 0; j < 4; j++) S[i][j] = fmaf(a[i], bb[j], S[i][j]);
        }

        // scale + causal mask
        const bool diag = (kt == qt);
#pragma unroll
        for (int i = 0; i < 4; i++) {
            int qr = qt * 64 + ty + 16 * i;
#pragma unroll
            for (int j = 0; j < 4; j++) {
                int kc = kt * 64 + tx + 16 * j;
                S[i][j] = (!diag || kc <= qr) ? S[i][j] * scale : -1e30f;
            }
        }

        // online softmax per row (row = 16 consecutive lanes)
#pragma unroll
        for (int i = 0; i < 4; i++) {
            float pm = fmaxf(fmaxf(S[i][0], S[i][1]), fmaxf(S[i][2], S[i][3]));
#pragma unroll
            for (int o = 8; o >= 1; o >>= 1)
                pm = fmaxf(pm, __shfl_xor_sync(0xffffffffu, pm, o, 16));
            float mn = fmaxf(m[i], pm);
            float corr = __expf(m[i] - mn);
            m[i] = mn;

            float rs = 0.0f;
#pragma unroll
            for (int j = 0; j < 4; j++) {
                float p = __expf(S[i][j] - mn);
                S[i][j] = p;
                rs += p;
            }
#pragma unroll
            for (int o = 8; o >= 1; o >>= 1)
                rs += __shfl_xor_sync(0xffffffffu, rs, o, 16);
            l[i] = l[i] * corr + rs;
#pragma unroll
            for (int j = 0; j < 4; j++) O[i][j] *= corr;
        }

        // stage P to smem
#pragma unroll
        for (int i = 0; i < 4; i++)
#pragma unroll
            for (int j = 0; j < 4; j++)
                Ps[(ty + 16 * i) * PAD + (tx + 16 * j)] = S[i][j];
        __syncthreads();

        // O += P @ V
#pragma unroll 8
        for (int c = 0; c < 64; c++) {
            float p[4], vv[4];
#pragma unroll
            for (int i = 0; i < 4; i++) p[i]  = Ps[(ty + 16 * i) * PAD + c];
#pragma unroll
            for (int j = 0; j < 4; j++) vv[j] = Vs[c * PAD + (tx + 16 * j)];
#pragma unroll
            for (int i = 0; i < 4; i++)
#pragma unroll
                for (int j = 0; j < 4; j++) O[i][j] = fmaf(p[i], vv[j], O[i][j]);
        }
    }

    // epilogue: normalize and write
#pragma unroll
    for (int i = 0; i < 4; i++) {
        long qr = (long)qt * 64 + ty + 16 * i;
        float inv = 1.0f / l[i];
#pragma unroll
        for (int j = 0; j < 4; j++) {
            int h = tx + 16 * j;
            out[((long)b * T_ + qr) * H_ + h] = O[i][j] * inv;
        }
    }
}

// ---------------------------------------------------------------------------
extern "C" void kernel_launch(void* const* d_in, const int* in_sizes, int n_in,
                              void* d_out, int out_size)
{
    const float* x  = (const float*)d_in[0];
    const float* Wk = (const float*)d_in[1];
    const float* Wq = (const float*)d_in[2];
    const float* Wv = (const float*)d_in[3];
    float* out = (float*)d_out;

    qkv_proj<<<NROW / 64, 256>>>(x, Wk, Wq, Wv);

    const int smem = 4 * 64 * PAD * (int)sizeof(float);  // 66560 B
    cudaFuncSetAttribute(flash_attn, cudaFuncAttributeMaxDynamicSharedMemorySize, smem);
    flash_attn<<<dim3(T_ / 64, B_), 256, smem>>>(out);
}

// round 3
// speedup vs baseline: 1.6501x; 1.6501x over previous
#include <cuda_runtime.h>
#include <cuda_bf16.h>
#include <cstdint>

#define B_ 8
#define T_ 2048
#define C_ 1024
#define H_ 64
#define NROW (B_*T_)
#define PK 40   // proj smem k-stride (bf16) — conflict-free for frag loads
#define PT 72   // flash smem stride (bf16) — conflict-free for frag loads

// bf16 hi/lo split intermediates (device globals: allocation-free scratch)
__device__ __nv_bfloat16 g_qh[NROW*H_];
__device__ __nv_bfloat16 g_ql[NROW*H_];
__device__ __nv_bfloat16 g_kh[NROW*H_];
__device__ __nv_bfloat16 g_kl[NROW*H_];
__device__ __nv_bfloat16 g_vh[B_*H_*T_];   // [b][h][t] transposed
__device__ __nv_bfloat16 g_vl[B_*H_*T_];

// ---------------------------------------------------------------------------
__device__ __forceinline__ void mma_bf16(float* c, const uint32_t* a,
                                         uint32_t b0, uint32_t b1) {
    asm volatile("mma.sync.aligned.m16n8k16.row.col.f32.bf16.bf16.f32 "
        "{%0,%1,%2,%3}, {%4,%5,%6,%7}, {%8,%9}, {%0,%1,%2,%3};"
        : "+f"(c[0]), "+f"(c[1]), "+f"(c[2]), "+f"(c[3])
        : "r"(a[0]), "r"(a[1]), "r"(a[2]), "r"(a[3]), "r"(b0), "r"(b1));
}

__device__ __forceinline__ void split1(float v, __nv_bfloat16& h, __nv_bfloat16& l) {
    h = __float2bfloat16_rn(v);
    l = __float2bfloat16_rn(v - __bfloat162float(h));
}
__device__ __forceinline__ uint32_t packb(__nv_bfloat16 e0, __nv_bfloat16 e1) {
    return (uint32_t)__bfloat16_as_ushort(e0) |
           ((uint32_t)__bfloat16_as_ushort(e1) << 16);
}
// split two floats, pack (e0,e1) hi-word pair and lo-word pair
__device__ __forceinline__ void split_pack(float a, float b, uint32_t& hi, uint32_t& lo) {
    __nv_bfloat16 ah, al, bh, bl;
    split1(a, ah, al);
    split1(b, bh, bl);
    hi = packb(ah, bh);
    lo = packb(al, bl);
}

// ---------------------------------------------------------------------------
// Kernel 1: QKV projection, bf16x3 mma.sync.
// Block: 256 thr (8 warps = 2M x 4N), M-tile 64, N = 192 (q|k|v), K chunks 32.
// ---------------------------------------------------------------------------
struct ProjS {
    __nv_bfloat16 xh[2][64*PK];
    __nv_bfloat16 xl[2][64*PK];
    __nv_bfloat16 wh[2][192*PK];
    __nv_bfloat16 wl[2][192*PK];
};

__global__ __launch_bounds__(256, 1) void qkv_proj(
    const float* __restrict__ x, const float* __restrict__ Wk,
    const float* __restrict__ Wq, const float* __restrict__ Wv)
{
    extern __shared__ char smraw[];
    ProjS* sm = reinterpret_cast<ProjS*>(smraw);
    const int tid = threadIdx.x, lane = tid & 31, wid = tid >> 5;
    const int g = lane >> 2, tg = lane & 3;
    const int m0 = 32 * (wid >> 2);
    const int n0 = 48 * (wid & 3);
    const size_t rowBase = (size_t)blockIdx.x * 64;

    float acc[2][6][4];
#pragma unroll
    for (int a = 0; a < 2; a++)
#pragma unroll
        for (int b = 0; b < 6; b++)
#pragma unroll
            for (int c = 0; c < 4; c++) acc[a][b][c] = 0.0f;

    float4 xr[2], wr[6];
    // prologue: load chunk 0 into regs
#pragma unroll
    for (int i = 0; i < 2; i++) {
        int slot = tid + 256*i; int r = slot >> 3; int c = (slot & 7) * 4;
        xr[i] = *(const float4*)(x + (rowBase + r) * C_ + c);
    }
#pragma unroll
    for (int i = 0; i < 6; i++) {
        int slot = tid + 256*i; int k = slot / 48; int f = slot % 48;
        const float* W = (f < 16) ? Wq : ((f < 32) ? Wk : Wv);
        int n = (f & 15) * 4;
        wr[i] = *(const float4*)(W + (size_t)k * H_ + n);
    }

    for (int it = 0; it < 32; ++it) {
        const int s = it & 1;
        // convert + store staged regs into stage s
#pragma unroll
        for (int i = 0; i < 2; i++) {
            int slot = tid + 256*i; int r = slot >> 3; int c = (slot & 7) * 4;
            uint32_t h0, l0, h1, l1;
            split_pack(xr[i].x, xr[i].y, h0, l0);
            split_pack(xr[i].z, xr[i].w, h1, l1);
            uint32_t* ph = reinterpret_cast<uint32_t*>(&sm->xh[s][r*PK + c]);
            uint32_t* pl = reinterpret_cast<uint32_t*>(&sm->xl[s][r*PK + c]);
            ph[0] = h0; ph[1] = h1;
            pl[0] = l0; pl[1] = l1;
        }
#pragma unroll
        for (int i = 0; i < 6; i++) {
            int slot = tid + 256*i; int k = slot / 48; int f = slot % 48;
            int nb = (f >> 4) * 64 + (f & 15) * 4;
            float v[4] = { wr[i].x, wr[i].y, wr[i].z, wr[i].w };
#pragma unroll
            for (int j = 0; j < 4; j++) {
                __nv_bfloat16 h, l; split1(v[j], h, l);
                sm->wh[s][(nb + j)*PK + k] = h;
                sm->wl[s][(nb + j)*PK + k] = l;
            }
        }
        __syncthreads();

        // prefetch next chunk (overlaps with mma below)
        if (it < 31) {
            const int kt = (it + 1) * 32;
#pragma unroll
            for (int i = 0; i < 2; i++) {
                int slot = tid + 256*i; int r = slot >> 3; int c = (slot & 7) * 4;
                xr[i] = *(const float4*)(x + (rowBase + r) * C_ + kt + c);
            }
#pragma unroll
            for (int i = 0; i < 6; i++) {
                int slot = tid + 256*i; int k = slot / 48; int f = slot % 48;
                const float* W = (f < 16) ? Wq : ((f < 32) ? Wk : Wv);
                int n = (f & 15) * 4;
                wr[i] = *(const float4*)(W + (size_t)(kt + k) * H_ + n);
            }
        }

        // compute: 2 ksteps x 6 ntiles x 2 mtiles x 3 passes
        const uint32_t* xhp = reinterpret_cast<const uint32_t*>(sm->xh[s]);
        const uint32_t* xlp = reinterpret_cast<const uint32_t*>(sm->xl[s]);
        const uint32_t* whp = reinterpret_cast<const uint32_t*>(sm->wh[s]);
        const uint32_t* wlp = reinterpret_cast<const uint32_t*>(sm->wl[s]);
#pragma unroll
        for (int ks = 0; ks < 2; ks++) {
            const int kw = tg + 8*ks;
            uint32_t ah[2][4], al[2][4];
#pragma unroll
            for (int mt = 0; mt < 2; mt++) {
                int r = m0 + 16*mt + g;
                ah[mt][0] = xhp[r*20 + kw];
                ah[mt][1] = xhp[(r+8)*20 + kw];
                ah[mt][2] = xhp[r*20 + kw + 4];
                ah[mt][3] = xhp[(r+8)*20 + kw + 4];
                al[mt][0] = xlp[r*20 + kw];
                al[mt][1] = xlp[(r+8)*20 + kw];
                al[mt][2] = xlp[r*20 + kw + 4];
                al[mt][3] = xlp[(r+8)*20 + kw + 4];
            }
#pragma unroll
            for (int nt = 0; nt < 6; nt++) {
                int n = n0 + 8*nt + g;
                uint32_t bh0 = whp[n*20 + kw], bh1 = whp[n*20 + kw + 4];
                uint32_t bl0 = wlp[n*20 + kw], bl1 = wlp[n*20 + kw + 4];
#pragma unroll
                for (int mt = 0; mt < 2; mt++) {
                    mma_bf16(acc[mt][nt], ah[mt], bh0, bh1);
                    mma_bf16(acc[mt][nt], ah[mt], bl0, bl1);
                    mma_bf16(acc[mt][nt], al[mt], bh0, bh1);
                }
            }
        }
    }

    // epilogue: split+store q (pre-scaled), k row-major, v transposed
    const float qscale = 0.03125f;   // C^-0.5
#pragma unroll
    for (int mt = 0; mt < 2; mt++) {
#pragma unroll
        for (int nt = 0; nt < 6; nt++) {
            int gc = n0 + 8*nt;
            float* c = acc[mt][nt];
            int r0 = m0 + 16*mt + g;
            size_t row0 = rowBase + r0, row1 = row0 + 8;
            if (gc < 64) {
                int col = gc + 2*tg;
                uint32_t h, l;
                split_pack(c[0]*qscale, c[1]*qscale, h, l);
                *reinterpret_cast<uint32_t*>(&g_qh[row0*H_ + col]) = h;
                *reinterpret_cast<uint32_t*>(&g_ql[row0*H_ + col]) = l;
                split_pack(c[2]*qscale, c[3]*qscale, h, l);
                *reinterpret_cast<uint32_t*>(&g_qh[row1*H_ + col]) = h;
                *reinterpret_cast<uint32_t*>(&g_ql[row1*H_ + col]) = l;
            } else if (gc < 128) {
                int col = gc - 64 + 2*tg;
                uint32_t h, l;
                split_pack(c[0], c[1], h, l);
                *reinterpret_cast<uint32_t*>(&g_kh[row0*H_ + col]) = h;
                *reinterpret_cast<uint32_t*>(&g_kl[row0*H_ + col]) = l;
                split_pack(c[2], c[3], h, l);
                *reinterpret_cast<uint32_t*>(&g_kh[row1*H_ + col]) = h;
                *reinterpret_cast<uint32_t*>(&g_kl[row1*H_ + col]) = l;
            } else {
                int h0 = gc - 128 + 2*tg;
                size_t bb = rowBase >> 11;            // batch
                size_t tb = (rowBase & 2047);
                __nv_bfloat16 hh, ll;
                split1(c[0], hh, ll);
                g_vh[(bb*H_ + h0    )*T_ + tb + r0] = hh;
                g_vl[(bb*H_ + h0    )*T_ + tb + r0] = ll;
                split1(c[1], hh, ll);
                g_vh[(bb*H_ + h0 + 1)*T_ + tb + r0] = hh;
                g_vl[(bb*H_ + h0 + 1)*T_ + tb + r0] = ll;
                split1(c[2], hh, ll);
                g_vh[(bb*H_ + h0    )*T_ + tb + r0 + 8] = hh;
                g_vl[(bb*H_ + h0    )*T_ + tb + r0 + 8] = ll;
                split1(c[3], hh, ll);
                g_vh[(bb*H_ + h0 + 1)*T_ + tb + r0 + 8] = hh;
                g_vl[(bb*H_ + h0 + 1)*T_ + tb + r0 + 8] = ll;
            }
        }
    }
}

// ---------------------------------------------------------------------------
// Kernel 2: causal flash attention, bf16x3 mma.sync.
// Block: 128 thr (4 warps), 64 q rows (warp w: rows 16w..16w+15), kv tiles 64.
// ---------------------------------------------------------------------------
struct FaS {
    __nv_bfloat16 qh[64*PT], ql[64*PT];
    __nv_bfloat16 kh[64*PT], kl[64*PT];
    __nv_bfloat16 vh[64*PT], vl[64*PT];   // [h][t]
};

__global__ __launch_bounds__(128, 1) void flash_mma(float* __restrict__ out)
{
    extern __shared__ char smraw[];
    FaS* sm = reinterpret_cast<FaS*>(smraw);
    const int tid = threadIdx.x, lane = tid & 31;
    const int g = lane >> 2, tg = lane & 3;
    const int m0 = 16 * (tid >> 5);
    const int blk = blockIdx.x;
    const int qt = 31 - (blk >> 3);   // heavy tiles first
    const int b  = blk & 7;

    // load Q tile (pre-scaled by C^-0.5 at projection)
    {
        const __nv_bfloat16* sh = g_qh + (size_t)(b*T_ + qt*64) * H_;
        const __nv_bfloat16* sl = g_ql + (size_t)(b*T_ + qt*64) * H_;
#pragma unroll
        for (int i = 0; i < 4; i++) {
            int slot = tid + 128*i; int r = slot >> 3; int c = (slot & 7) * 8;
            *(uint4*)&sm->qh[r*PT + c] = *(const uint4*)(sh + r*H_ + c);
            *(uint4*)&sm->ql[r*PT + c] = *(const uint4*)(sl + r*H_ + c);
        }
    }

    float O[8][4];
#pragma unroll
    for (int a = 0; a < 8; a++)
#pragma unroll
        for (int c = 0; c < 4; c++) O[a][c] = 0.0f;
    float mr[2] = { -1e30f, -1e30f }, lr[2] = { 0.0f, 0.0f };

    for (int kvt = 0; kvt <= qt; ++kvt) {
        __syncthreads();
        {
            const __nv_bfloat16* khs = g_kh + (size_t)(b*T_ + kvt*64) * H_;
            const __nv_bfloat16* kls = g_kl + (size_t)(b*T_ + kvt*64) * H_;
            const __nv_bfloat16* vhs = g_vh + (size_t)b*H_*T_ + kvt*64;
            const __nv_bfloat16* vls = g_vl + (size_t)b*H_*T_ + kvt*64;
#pragma unroll
            for (int i = 0; i < 4; i++) {
                int slot = tid + 128*i; int r = slot >> 3; int c = (slot & 7) * 8;
                *(uint4*)&sm->kh[r*PT + c] = *(const uint4*)(khs + r*H_ + c);
                *(uint4*)&sm->kl[r*PT + c] = *(const uint4*)(kls + r*H_ + c);
                *(uint4*)&sm->vh[r*PT + c] = *(const uint4*)(vhs + (size_t)r*T_ + c);
                *(uint4*)&sm->vl[r*PT + c] = *(const uint4*)(vls + (size_t)r*T_ + c);
            }
        }
        __syncthreads();

        // S = Q @ K^T, 3-pass
        float Sf[8][4];
#pragma unroll
        for (int a = 0; a < 8; a++)
#pragma unroll
            for (int c = 0; c < 4; c++) Sf[a][c] = 0.0f;

        const uint32_t* qhp = reinterpret_cast<const uint32_t*>(sm->qh);
        const uint32_t* qlp = reinterpret_cast<const uint32_t*>(sm->ql);
        const uint32_t* khp = reinterpret_cast<const uint32_t*>(sm->kh);
        const uint32_t* klp = reinterpret_cast<const uint32_t*>(sm->kl);
#pragma unroll
        for (int ks = 0; ks < 4; ks++) {
            const int kw = tg + 8*ks;
            uint32_t ah[4], al[4];
            int r = m0 + g;
            ah[0] = qhp[r*36 + kw];       ah[1] = qhp[(r+8)*36 + kw];
            ah[2] = qhp[r*36 + kw + 4];   ah[3] = qhp[(r+8)*36 + kw + 4];
            al[0] = qlp[r*36 + kw];       al[1] = qlp[(r+8)*36 + kw];
            al[2] = qlp[r*36 + kw + 4];   al[3] = qlp[(r+8)*36 + kw + 4];
#pragma unroll
            for (int nt = 0; nt < 8; nt++) {
                int n = 8*nt + g;
                uint32_t bh0 = khp[n*36 + kw], bh1 = khp[n*36 + kw + 4];
                uint32_t bl0 = klp[n*36 + kw], bl1 = klp[n*36 + kw + 4];
                mma_bf16(Sf[nt], ah, bh0, bh1);
                mma_bf16(Sf[nt], ah, bl0, bl1);
                mma_bf16(Sf[nt], al, bh0, bh1);
            }
        }

        // causal mask on diagonal tile (local coords: same 64-block)
        if (kvt == qt) {
#pragma unroll
            for (int nt = 0; nt < 8; nt++) {
                int colb = 8*nt + 2*tg;
                int row0 = m0 + g, row1 = row0 + 8;
                if (colb     > row0) Sf[nt][0] = -1e30f;
                if (colb + 1 > row0) Sf[nt][1] = -1e30f;
                if (colb     > row1) Sf[nt][2] = -1e30f;
                if (colb + 1 > row1) Sf[nt][3] = -1e30f;
            }
        }

        // online softmax: two rows per lane (g and g+8)
#pragma unroll
        for (int rr = 0; rr < 2; rr++) {
            float mx = -1e30f;
#pragma unroll
            for (int nt = 0; nt < 8; nt++)
                mx = fmaxf(mx, fmaxf(Sf[nt][2*rr], Sf[nt][2*rr+1]));
            mx = fmaxf(mx, __shfl_xor_sync(0xffffffffu, mx, 1));
            mx = fmaxf(mx, __shfl_xor_sync(0xffffffffu, mx, 2));
            float mn = fmaxf(mr[rr], mx);
            float corr = __expf(mr[rr] - mn);
            mr[rr] = mn;
            float sum = 0.0f;
#pragma unroll
            for (int nt = 0; nt < 8; nt++) {
                float p0 = __expf(Sf[nt][2*rr]   - mn);
                float p1 = __expf(Sf[nt][2*rr+1] - mn);
                Sf[nt][2*rr] = p0; Sf[nt][2*rr+1] = p1;
                sum += p0 + p1;
            }
            sum += __shfl_xor_sync(0xffffffffu, sum, 1);
            sum += __shfl_xor_sync(0xffffffffu, sum, 2);
            lr[rr] = lr[rr]*corr + sum;
#pragma unroll
            for (int nt = 0; nt < 8; nt++) {
                O[nt][2*rr]   *= corr;
                O[nt][2*rr+1] *= corr;
            }
        }

        // O += P @ V  (P re-split to bf16 hi/lo directly in A-fragment layout)
        const uint32_t* vhp = reinterpret_cast<const uint32_t*>(sm->vh);
        const uint32_t* vlp = reinterpret_cast<const uint32_t*>(sm->vl);
#pragma unroll
        for (int ks = 0; ks < 4; ks++) {
            uint32_t ph[4], pl[4];
            split_pack(Sf[2*ks][0],   Sf[2*ks][1],   ph[0], pl[0]);
            split_pack(Sf[2*ks][2],   Sf[2*ks][3],   ph[1], pl[1]);
            split_pack(Sf[2*ks+1][0], Sf[2*ks+1][1], ph[2], pl[2]);
            split_pack(Sf[2*ks+1][2], Sf[2*ks+1][3], ph[3], pl[3]);
            const int kw = tg + 8*ks;
#pragma unroll
            for (int nt = 0; nt < 8; nt++) {
                int n = 8*nt + g;
                uint32_t bh0 = vhp[n*36 + kw], bh1 = vhp[n*36 + kw + 4];
                uint32_t bl0 = vlp[n*36 + kw], bl1 = vlp[n*36 + kw + 4];
                mma_bf16(O[nt], ph, bh0, bh1);
                mma_bf16(O[nt], ph, bl0, bl1);
                mma_bf16(O[nt], pl, bh0, bh1);
            }
        }
    }

    // epilogue: normalize and store fp32
    float inv0 = 1.0f / lr[0], inv1 = 1.0f / lr[1];
    size_t row0 = (size_t)b*T_ + (size_t)qt*64 + m0 + g;
    size_t row1 = row0 + 8;
#pragma unroll
    for (int nt = 0; nt < 8; nt++) {
        int col = 8*nt + 2*tg;
        float2 v0 = { O[nt][0]*inv0, O[nt][1]*inv0 };
        float2 v1 = { O[nt][2]*inv1, O[nt][3]*inv1 };
        *reinterpret_cast<float2*>(out + row0*H_ + col) = v0;
        *reinterpret_cast<float2*>(out + row1*H_ + col) = v1;
    }
}

// ---------------------------------------------------------------------------
extern "C" void kernel_launch(void* const* d_in, const int* in_sizes, int n_in,
                              void* d_out, int out_size)
{
    const float* x  = (const float*)d_in[0];
    const float* Wk = (const float*)d_in[1];
    const float* Wq = (const float*)d_in[2];
    const float* Wv = (const float*)d_in[3];
    float* out = (float*)d_out;

    const int psm = (int)sizeof(ProjS);   // 81920
    cudaFuncSetAttribute(qkv_proj, cudaFuncAttributeMaxDynamicSharedMemorySize, psm);
    qkv_proj<<<NROW / 64, 256, psm>>>(x, Wk, Wq, Wv);

    const int fsm = (int)sizeof(FaS);     // 55296
    cudaFuncSetAttribute(flash_mma, cudaFuncAttributeMaxDynamicSharedMemorySize, fsm);
    flash_mma<<<(T_/64) * B_, 128, fsm>>>(out);
}

// round 4
// speedup vs baseline: 3.0436x; 1.8445x over previous
#include <cuda_runtime.h>
#include <cuda_bf16.h>
#include <cstdint>

#define B_ 8
#define T_ 2048
#define C_ 1024
#define H_ 64
#define NROW (B_*T_)
#define PK 40   // proj smem k-stride (bf16)
#define PT 72   // flash smem stride (bf16)

// pre-split inputs
__device__ __nv_bfloat16 g_xh[NROW*C_];
__device__ __nv_bfloat16 g_xl[NROW*C_];
__device__ __nv_bfloat16 g_wh[192*C_];   // [n][k], n: 0-63 q, 64-127 k, 128-191 v
__device__ __nv_bfloat16 g_wl[192*C_];

// projection outputs (bf16 hi/lo)
__device__ __nv_bfloat16 g_qh[NROW*H_];
__device__ __nv_bfloat16 g_ql[NROW*H_];
__device__ __nv_bfloat16 g_kh[NROW*H_];
__device__ __nv_bfloat16 g_kl[NROW*H_];
__device__ __nv_bfloat16 g_vh[B_*H_*T_];   // [b][h][t]
__device__ __nv_bfloat16 g_vl[B_*H_*T_];

// ---------------------------------------------------------------------------
__device__ __forceinline__ void mma_bf16(float* c, const uint32_t* a,
                                         uint32_t b0, uint32_t b1) {
    asm volatile("mma.sync.aligned.m16n8k16.row.col.f32.bf16.bf16.f32 "
        "{%0,%1,%2,%3}, {%4,%5,%6,%7}, {%8,%9}, {%0,%1,%2,%3};"
        : "+f"(c[0]), "+f"(c[1]), "+f"(c[2]), "+f"(c[3])
        : "r"(a[0]), "r"(a[1]), "r"(a[2]), "r"(a[3]), "r"(b0), "r"(b1));
}
__device__ __forceinline__ void split1(float v, __nv_bfloat16& h, __nv_bfloat16& l) {
    h = __float2bfloat16_rn(v);
    l = __float2bfloat16_rn(v - __bfloat162float(h));
}
__device__ __forceinline__ uint32_t packb(__nv_bfloat16 e0, __nv_bfloat16 e1) {
    return (uint32_t)__bfloat16_as_ushort(e0) |
           ((uint32_t)__bfloat16_as_ushort(e1) << 16);
}
__device__ __forceinline__ void split_pack(float a, float b, uint32_t& hi, uint32_t& lo) {
    __nv_bfloat16 ah, al, bh, bl;
    split1(a, ah, al); split1(b, bh, bl);
    hi = packb(ah, bh); lo = packb(al, bl);
}

// ---------------------------------------------------------------------------
// Kernel 0a: split W into bf16 hi/lo, transposed to [n][k].
// 192*1024 elems, 4 per thread. grid 192, block 256.
// ---------------------------------------------------------------------------
__global__ void wconv(const float* __restrict__ Wk, const float* __restrict__ Wq,
                      const float* __restrict__ Wv)
{
    int slot = blockIdx.x * 256 + threadIdx.x;       // 49152 slots
    int k  = slot >> 4;                              // 0..3071 -> (mat,k)
    int nq = (slot & 15) * 4;
    int mat = k >> 10;                               // 0=q,1=k,2=v
    int kk = k & 1023;
    const float* W = (mat == 0) ? Wq : ((mat == 1) ? Wk : Wv);
    float4 v = *(const float4*)(W + (size_t)kk * H_ + nq);
    float f[4] = { v.x, v.y, v.z, v.w };
#pragma unroll
    for (int j = 0; j < 4; j++) {
        __nv_bfloat16 h, l; split1(f[j], h, l);
        size_t o = (size_t)(mat * 64 + nq + j) * C_ + kk;
        g_wh[o] = h; g_wl[o] = l;
    }
}

// ---------------------------------------------------------------------------
// Kernel 0b: split x into bf16 hi/lo (row-major, same layout).
// ---------------------------------------------------------------------------
__global__ __launch_bounds__(256) void xconv(const float* __restrict__ x)
{
    size_t i4 = (size_t)blockIdx.x * 256 + threadIdx.x;   // float4 index
    float4 v = *(const float4*)(x + i4 * 4);
    __nv_bfloat16 h0,l0,h1,l1,h2,l2,h3,l3;
    split1(v.x,h0,l0); split1(v.y,h1,l1); split1(v.z,h2,l2); split1(v.w,h3,l3);
    uint2 ph = { packb(h0,h1), packb(h2,h3) };
    uint2 pl = { packb(l0,l1), packb(l2,l3) };
    *reinterpret_cast<uint2*>(&g_xh[i4 * 4]) = ph;
    *reinterpret_cast<uint2*>(&g_xl[i4 * 4]) = pl;
}

// ---------------------------------------------------------------------------
// Kernel 1: QKV projection GEMM, pure bf16x3 mma (inputs pre-split).
// Block: 256 thr (8 warps = 2M x 4N), M-tile 64, N = 192, K chunks 32,
// double-buffered smem, register-staged prefetch.
// ---------------------------------------------------------------------------
struct ProjS {
    __nv_bfloat16 xh[2][64*PK];
    __nv_bfloat16 xl[2][64*PK];
    __nv_bfloat16 wh[2][192*PK];
    __nv_bfloat16 wl[2][192*PK];
};

__global__ __launch_bounds__(256, 2) void qkv_proj()
{
    extern __shared__ char smraw[];
    ProjS* sm = reinterpret_cast<ProjS*>(smraw);
    const int tid = threadIdx.x, lane = tid & 31, wid = tid >> 5;
    const int g = lane >> 2, tg = lane & 3;
    const int m0 = 32 * (wid >> 2);
    const int n0 = 48 * (wid & 3);
    const size_t rowBase = (size_t)blockIdx.x * 64;

    // A copy mapping: slot=tid -> r=tid>>2, c8=(tid&3)*8  (256 uint4)
    const int ar = tid >> 2, ac = (tid & 3) * 8;
    // B copy mapping: slot=tid+256*i -> n=slot>>2, c8=(slot&3)*8 (768 uint4)

    float acc[2][6][4];
#pragma unroll
    for (int a = 0; a < 2; a++)
#pragma unroll
        for (int b = 0; b < 6; b++)
#pragma unroll
            for (int c = 0; c < 4; c++) acc[a][b][c] = 0.0f;

    uint4 rxh, rxl, rwh[3], rwl[3];
    // prologue: chunk 0
    rxh = *(const uint4*)(g_xh + (rowBase + ar) * C_ + ac);
    rxl = *(const uint4*)(g_xl + (rowBase + ar) * C_ + ac);
#pragma unroll
    for (int i = 0; i < 3; i++) {
        int slot = tid + 256*i; int n = slot >> 2; int c8 = (slot & 3) * 8;
        rwh[i] = *(const uint4*)(g_wh + (size_t)n * C_ + c8);
        rwl[i] = *(const uint4*)(g_wl + (size_t)n * C_ + c8);
    }

    for (int it = 0; it < 32; ++it) {
        const int s = it & 1;
        // store staged regs
        *(uint4*)&sm->xh[s][ar*PK + ac] = rxh;
        *(uint4*)&sm->xl[s][ar*PK + ac] = rxl;
#pragma unroll
        for (int i = 0; i < 3; i++) {
            int slot = tid + 256*i; int n = slot >> 2; int c8 = (slot & 3) * 8;
            *(uint4*)&sm->wh[s][n*PK + c8] = rwh[i];
            *(uint4*)&sm->wl[s][n*PK + c8] = rwl[i];
        }
        __syncthreads();

        // prefetch next chunk
        if (it < 31) {
            const int kt = (it + 1) * 32;
            rxh = *(const uint4*)(g_xh + (rowBase + ar) * C_ + kt + ac);
            rxl = *(const uint4*)(g_xl + (rowBase + ar) * C_ + kt + ac);
#pragma unroll
            for (int i = 0; i < 3; i++) {
                int slot = tid + 256*i; int n = slot >> 2; int c8 = (slot & 3) * 8;
                rwh[i] = *(const uint4*)(g_wh + (size_t)n * C_ + kt + c8);
                rwl[i] = *(const uint4*)(g_wl + (size_t)n * C_ + kt + c8);
            }
        }

        const uint32_t* xhp = reinterpret_cast<const uint32_t*>(sm->xh[s]);
        const uint32_t* xlp = reinterpret_cast<const uint32_t*>(sm->xl[s]);
        const uint32_t* whp = reinterpret_cast<const uint32_t*>(sm->wh[s]);
        const uint32_t* wlp = reinterpret_cast<const uint32_t*>(sm->wl[s]);
#pragma unroll
        for (int ks = 0; ks < 2; ks++) {
            const int kw = tg + 8*ks;
            uint32_t ah[2][4], al[2][4];
#pragma unroll
            for (int mt = 0; mt < 2; mt++) {
                int r = m0 + 16*mt + g;
                ah[mt][0] = xhp[r*20 + kw];      ah[mt][1] = xhp[(r+8)*20 + kw];
                ah[mt][2] = xhp[r*20 + kw + 4];  ah[mt][3] = xhp[(r+8)*20 + kw + 4];
                al[mt][0] = xlp[r*20 + kw];      al[mt][1] = xlp[(r+8)*20 + kw];
                al[mt][2] = xlp[r*20 + kw + 4];  al[mt][3] = xlp[(r+8)*20 + kw + 4];
            }
#pragma unroll
            for (int nt = 0; nt < 6; nt++) {
                int n = n0 + 8*nt + g;
                uint32_t bh0 = whp[n*20 + kw], bh1 = whp[n*20 + kw + 4];
                uint32_t bl0 = wlp[n*20 + kw], bl1 = wlp[n*20 + kw + 4];
#pragma unroll
                for (int mt = 0; mt < 2; mt++) {
                    mma_bf16(acc[mt][nt], ah[mt], bh0, bh1);
                    mma_bf16(acc[mt][nt], ah[mt], bl0, bl1);
                    mma_bf16(acc[mt][nt], al[mt], bh0, bh1);
                }
            }
        }
        __syncthreads();
    }

    // epilogue: split+store q (pre-scaled), k row-major, v transposed
    const float qscale = 0.03125f;   // C^-0.5
#pragma unroll
    for (int mt = 0; mt < 2; mt++) {
#pragma unroll
        for (int nt = 0; nt < 6; nt++) {
            int gc = n0 + 8*nt;
            float* c = acc[mt][nt];
            int r0 = m0 + 16*mt + g;
            size_t row0 = rowBase + r0, row1 = row0 + 8;
            if (gc < 64) {
                int col = gc + 2*tg;
                uint32_t h, l;
                split_pack(c[0]*qscale, c[1]*qscale, h, l);
                *reinterpret_cast<uint32_t*>(&g_qh[row0*H_ + col]) = h;
                *reinterpret_cast<uint32_t*>(&g_ql[row0*H_ + col]) = l;
                split_pack(c[2]*qscale, c[3]*qscale, h, l);
                *reinterpret_cast<uint32_t*>(&g_qh[row1*H_ + col]) = h;
                *reinterpret_cast<uint32_t*>(&g_ql[row1*H_ + col]) = l;
            } else if (gc < 128) {
                int col = gc - 64 + 2*tg;
                uint32_t h, l;
                split_pack(c[0], c[1], h, l);
                *reinterpret_cast<uint32_t*>(&g_kh[row0*H_ + col]) = h;
                *reinterpret_cast<uint32_t*>(&g_kl[row0*H_ + col]) = l;
                split_pack(c[2], c[3], h, l);
                *reinterpret_cast<uint32_t*>(&g_kh[row1*H_ + col]) = h;
                *reinterpret_cast<uint32_t*>(&g_kl[row1*H_ + col]) = l;
            } else {
                int h0 = gc - 128 + 2*tg;
                size_t bb = rowBase >> 11;
                size_t tb = (rowBase & 2047);
                __nv_bfloat16 hh, ll;
                split1(c[0], hh, ll);
                g_vh[(bb*H_ + h0    )*T_ + tb + r0] = hh;
                g_vl[(bb*H_ + h0    )*T_ + tb + r0] = ll;
                split1(c[1], hh, ll);
                g_vh[(bb*H_ + h0 + 1)*T_ + tb + r0] = hh;
                g_vl[(bb*H_ + h0 + 1)*T_ + tb + r0] = ll;
                split1(c[2], hh, ll);
                g_vh[(bb*H_ + h0    )*T_ + tb + r0 + 8] = hh;
                g_vl[(bb*H_ + h0    )*T_ + tb + r0 + 8] = ll;
                split1(c[3], hh, ll);
                g_vh[(bb*H_ + h0 + 1)*T_ + tb + r0 + 8] = hh;
                g_vl[(bb*H_ + h0 + 1)*T_ + tb + r0 + 8] = ll;
            }
        }
    }
}

// ---------------------------------------------------------------------------
// Kernel 2: causal flash attention, bf16x3 mma.sync (unchanged, known good).
// ---------------------------------------------------------------------------
struct FaS {
    __nv_bfloat16 qh[64*PT], ql[64*PT];
    __nv_bfloat16 kh[64*PT], kl[64*PT];
    __nv_bfloat16 vh[64*PT], vl[64*PT];
};

__global__ __launch_bounds__(128, 1) void flash_mma(float* __restrict__ out)
{
    extern __shared__ char smraw[];
    FaS* sm = reinterpret_cast<FaS*>(smraw);
    const int tid = threadIdx.x, lane = tid & 31;
    const int g = lane >> 2, tg = lane & 3;
    const int m0 = 16 * (tid >> 5);
    const int blk = blockIdx.x;
    const int qt = 31 - (blk >> 3);
    const int b  = blk & 7;

    {
        const __nv_bfloat16* sh = g_qh + (size_t)(b*T_ + qt*64) * H_;
        const __nv_bfloat16* sl = g_ql + (size_t)(b*T_ + qt*64) * H_;
#pragma unroll
        for (int i = 0; i < 4; i++) {
            int slot = tid + 128*i; int r = slot >> 3; int c = (slot & 7) * 8;
            *(uint4*)&sm->qh[r*PT + c] = *(const uint4*)(sh + r*H_ + c);
            *(uint4*)&sm->ql[r*PT + c] = *(const uint4*)(sl + r*H_ + c);
        }
    }

    float O[8][4];
#pragma unroll
    for (int a = 0; a < 8; a++)
#pragma unroll
        for (int c = 0; c < 4; c++) O[a][c] = 0.0f;
    float mr[2] = { -1e30f, -1e30f }, lr[2] = { 0.0f, 0.0f };

    for (int kvt = 0; kvt <= qt; ++kvt) {
        __syncthreads();
        {
            const __nv_bfloat16* khs = g_kh + (size_t)(b*T_ + kvt*64) * H_;
            const __nv_bfloat16* kls = g_kl + (size_t)(b*T_ + kvt*64) * H_;
            const __nv_bfloat16* vhs = g_vh + (size_t)b*H_*T_ + kvt*64;
            const __nv_bfloat16* vls = g_vl + (size_t)b*H_*T_ + kvt*64;
#pragma unroll
            for (int i = 0; i < 4; i++) {
                int slot = tid + 128*i; int r = slot >> 3; int c = (slot & 7) * 8;
                *(uint4*)&sm->kh[r*PT + c] = *(const uint4*)(khs + r*H_ + c);
                *(uint4*)&sm->kl[r*PT + c] = *(const uint4*)(kls + r*H_ + c);
                *(uint4*)&sm->vh[r*PT + c] = *(const uint4*)(vhs + (size_t)r*T_ + c);
                *(uint4*)&sm->vl[r*PT + c] = *(const uint4*)(vls + (size_t)r*T_ + c);
            }
        }
        __syncthreads();

        float Sf[8][4];
#pragma unroll
        for (int a = 0; a < 8; a++)
#pragma unroll
            for (int c = 0; c < 4; c++) Sf[a][c] = 0.0f;

        const uint32_t* qhp = reinterpret_cast<const uint32_t*>(sm->qh);
        const uint32_t* qlp = reinterpret_cast<const uint32_t*>(sm->ql);
        const uint32_t* khp = reinterpret_cast<const uint32_t*>(sm->kh);
        const uint32_t* klp = reinterpret_cast<const uint32_t*>(sm->kl);
#pragma unroll
        for (int ks = 0; ks < 4; ks++) {
            const int kw = tg + 8*ks;
            uint32_t ah[4], al[4];
            int r = m0 + g;
            ah[0] = qhp[r*36 + kw];       ah[1] = qhp[(r+8)*36 + kw];
            ah[2] = qhp[r*36 + kw + 4];   ah[3] = qhp[(r+8)*36 + kw + 4];
            al[0] = qlp[r*36 + kw];       al[1] = qlp[(r+8)*36 + kw];
            al[2] = qlp[r*36 + kw + 4];   al[3] = qlp[(r+8)*36 + kw + 4];
#pragma unroll
            for (int nt = 0; nt < 8; nt++) {
                int n = 8*nt + g;
                uint32_t bh0 = khp[n*36 + kw], bh1 = khp[n*36 + kw + 4];
                uint32_t bl0 = klp[n*36 + kw], bl1 = klp[n*36 + kw + 4];
                mma_bf16(Sf[nt], ah, bh0, bh1);
                mma_bf16(Sf[nt], ah, bl0, bl1);
                mma_bf16(Sf[nt], al, bh0, bh1);
            }
        }

        if (kvt == qt) {
#pragma unroll
            for (int nt = 0; nt < 8; nt++) {
                int colb = 8*nt + 2*tg;
                int row0 = m0 + g, row1 = row0 + 8;
                if (colb     > row0) Sf[nt][0] = -1e30f;
                if (colb + 1 > row0) Sf[nt][1] = -1e30f;
                if (colb     > row1) Sf[nt][2] = -1e30f;
                if (colb + 1 > row1) Sf[nt][3] = -1e30f;
            }
        }

#pragma unroll
        for (int rr = 0; rr < 2; rr++) {
            float mx = -1e30f;
#pragma unroll
            for (int nt = 0; nt < 8; nt++)
                mx = fmaxf(mx, fmaxf(Sf[nt][2*rr], Sf[nt][2*rr+1]));
            mx = fmaxf(mx, __shfl_xor_sync(0xffffffffu, mx, 1));
            mx = fmaxf(mx, __shfl_xor_sync(0xffffffffu, mx, 2));
            float mn = fmaxf(mr[rr], mx);
            float corr = __expf(mr[rr] - mn);
            mr[rr] = mn;
            float sum = 0.0f;
#pragma unroll
            for (int nt = 0; nt < 8; nt++) {
                float p0 = __expf(Sf[nt][2*rr]   - mn);
                float p1 = __expf(Sf[nt][2*rr+1] - mn);
                Sf[nt][2*rr] = p0; Sf[nt][2*rr+1] = p1;
                sum += p0 + p1;
            }
            sum += __shfl_xor_sync(0xffffffffu, sum, 1);
            sum += __shfl_xor_sync(0xffffffffu, sum, 2);
            lr[rr] = lr[rr]*corr + sum;
#pragma unroll
            for (int nt = 0; nt < 8; nt++) {
                O[nt][2*rr]   *= corr;
                O[nt][2*rr+1] *= corr;
            }
        }

        const uint32_t* vhp = reinterpret_cast<const uint32_t*>(sm->vh);
        const uint32_t* vlp = reinterpret_cast<const uint32_t*>(sm->vl);
#pragma unroll
        for (int ks = 0; ks < 4; ks++) {
            uint32_t ph[4], pl[4];
            split_pack(Sf[2*ks][0],   Sf[2*ks][1],   ph[0], pl[0]);
            split_pack(Sf[2*ks][2],   Sf[2*ks][3],   ph[1], pl[1]);
            split_pack(Sf[2*ks+1][0], Sf[2*ks+1][1], ph[2], pl[2]);
            split_pack(Sf[2*ks+1][2], Sf[2*ks+1][3], ph[3], pl[3]);
            const int kw = tg + 8*ks;
#pragma unroll
            for (int nt = 0; nt < 8; nt++) {
                int n = 8*nt + g;
                uint32_t bh0 = vhp[n*36 + kw], bh1 = vhp[n*36 + kw + 4];
                uint32_t bl0 = vlp[n*36 + kw], bl1 = vlp[n*36 + kw + 4];
                mma_bf16(O[nt], ph, bh0, bh1);
                mma_bf16(O[nt], ph, bl0, bl1);
                mma_bf16(O[nt], pl, bh0, bh1);
            }
        }
    }

    float inv0 = 1.0f / lr[0], inv1 = 1.0f / lr[1];
    size_t row0 = (size_t)b*T_ + (size_t)qt*64 + m0 + g;
    size_t row1 = row0 + 8;
#pragma unroll
    for (int nt = 0; nt < 8; nt++) {
        int col = 8*nt + 2*tg;
        float2 v0 = { O[nt][0]*inv0, O[nt][1]*inv0 };
        float2 v1 = { O[nt][2]*inv1, O[nt][3]*inv1 };
        *reinterpret_cast<float2*>(out + row0*H_ + col) = v0;
        *reinterpret_cast<float2*>(out + row1*H_ + col) = v1;
    }
}

// ---------------------------------------------------------------------------
extern "C" void kernel_launch(void* const* d_in, const int* in_sizes, int n_in,
                              void* d_out, int out_size)
{
    const float* x  = (const float*)d_in[0];
    const float* Wk = (const float*)d_in[1];
    const float* Wq = (const float*)d_in[2];
    const float* Wv = (const float*)d_in[3];
    float* out = (float*)d_out;

    wconv<<<192, 256>>>(Wk, Wq, Wv);
    xconv<<<NROW * C_ / 4 / 256, 256>>>(x);

    const int psm = (int)sizeof(ProjS);   // 81920
    cudaFuncSetAttribute(qkv_proj, cudaFuncAttributeMaxDynamicSharedMemorySize, psm);
    qkv_proj<<<NROW / 64, 256, psm>>>();

    const int fsm = (int)sizeof(FaS);
    cudaFuncSetAttribute(flash_mma, cudaFuncAttributeMaxDynamicSharedMemorySize, fsm);
    flash_mma<<<(T_/64) * B_, 128, fsm>>>(out);
}

// round 5
// speedup vs baseline: 3.9078x; 1.2839x over previous
#include <cuda_runtime.h>
#include <cuda_bf16.h>
#include <cstdint>

#define B_ 8
#define T_ 2048
#define C_ 1024
#define H_ 64
#define NROW (B_*T_)
#define PK 40   // proj smem k-stride (bf16)
#define PT 72   // flash smem stride (bf16)

// pre-split W (tiny); q/k/v outputs bf16 hi/lo
__device__ __nv_bfloat16 g_wh[192*C_];   // [n][k]
__device__ __nv_bfloat16 g_wl[192*C_];
__device__ __nv_bfloat16 g_qh[NROW*H_];
__device__ __nv_bfloat16 g_ql[NROW*H_];
__device__ __nv_bfloat16 g_kh[NROW*H_];
__device__ __nv_bfloat16 g_kl[NROW*H_];
__device__ __nv_bfloat16 g_vh[B_*H_*T_];   // [b][h][t]
__device__ __nv_bfloat16 g_vl[B_*H_*T_];

// ---------------------------------------------------------------------------
__device__ __forceinline__ void mma_bf16(float* c, const uint32_t* a,
                                         uint32_t b0, uint32_t b1) {
    asm volatile("mma.sync.aligned.m16n8k16.row.col.f32.bf16.bf16.f32 "
        "{%0,%1,%2,%3}, {%4,%5,%6,%7}, {%8,%9}, {%0,%1,%2,%3};"
        : "+f"(c[0]), "+f"(c[1]), "+f"(c[2]), "+f"(c[3])
        : "r"(a[0]), "r"(a[1]), "r"(a[2]), "r"(a[3]), "r"(b0), "r"(b1));
}
__device__ __forceinline__ void split1(float v, __nv_bfloat16& h, __nv_bfloat16& l) {
    h = __float2bfloat16_rn(v);
    l = __float2bfloat16_rn(v - __bfloat162float(h));
}
__device__ __forceinline__ uint32_t packb(__nv_bfloat16 e0, __nv_bfloat16 e1) {
    return (uint32_t)__bfloat16_as_ushort(e0) |
           ((uint32_t)__bfloat16_as_ushort(e1) << 16);
}
__device__ __forceinline__ void split_pack(float a, float b, uint32_t& hi, uint32_t& lo) {
    __nv_bfloat16 ah, al, bh, bl;
    split1(a, ah, al); split1(b, bh, bl);
    hi = packb(ah, bh); lo = packb(al, bl);
}
__device__ __forceinline__ uint32_t s2u(const void* p) {
    uint32_t a;
    asm("{ .reg .u64 t; cvta.to.shared.u64 t, %1; cvt.u32.u64 %0, t; }" : "=r"(a) : "l"(p));
    return a;
}
__device__ __forceinline__ void cpa16(uint32_t dst, const void* src) {
    asm volatile("cp.async.cg.shared.global [%0], [%1], 16;" :: "r"(dst), "l"(src) : "memory");
}
#define CP_COMMIT() asm volatile("cp.async.commit_group;" ::: "memory")
#define CP_WAIT1()  asm volatile("cp.async.wait_group 1;" ::: "memory")
#define CP_WAIT0()  asm volatile("cp.async.wait_group 0;" ::: "memory")

// ---------------------------------------------------------------------------
// Kernel 0: split W into bf16 hi/lo, transposed to [n][k].
// ---------------------------------------------------------------------------
__global__ void wconv(const float* __restrict__ Wk, const float* __restrict__ Wq,
                      const float* __restrict__ Wv)
{
    int slot = blockIdx.x * 256 + threadIdx.x;
    int k  = slot >> 4;
    int nq = (slot & 15) * 4;
    int mat = k >> 10;
    int kk = k & 1023;
    const float* W = (mat == 0) ? Wq : ((mat == 1) ? Wk : Wv);
    float4 v = *(const float4*)(W + (size_t)kk * H_ + nq);
    float f[4] = { v.x, v.y, v.z, v.w };
#pragma unroll
    for (int j = 0; j < 4; j++) {
        __nv_bfloat16 h, l; split1(f[j], h, l);
        size_t o = (size_t)(mat * 64 + nq + j) * C_ + kk;
        g_wh[o] = h; g_wl[o] = l;
    }
}

// ---------------------------------------------------------------------------
// Kernel 1: QKV projection, bf16x3 mma. x split fused in-loop (reg-staged),
// W hi/lo via cp.async double-buffer.
// ---------------------------------------------------------------------------
struct ProjS {
    __nv_bfloat16 xh[2][64*PK];
    __nv_bfloat16 xl[2][64*PK];
    __nv_bfloat16 wh[2][192*PK];
    __nv_bfloat16 wl[2][192*PK];
};

__global__ __launch_bounds__(256, 2) void qkv_proj(const float* __restrict__ x)
{
    extern __shared__ char smraw[];
    ProjS* sm = reinterpret_cast<ProjS*>(smraw);
    const int tid = threadIdx.x, lane = tid & 31, wid = tid >> 5;
    const int g = lane >> 2, tg = lane & 3;
    const int m0 = 32 * (wid >> 2);
    const int n0 = 48 * (wid & 3);
    const size_t rowBase = (size_t)blockIdx.x * 64;

    const int ar = tid >> 3, ac = (tid & 7) * 4;     // x: 512 float4 slots, 2/thread

    float acc[2][6][4];
#pragma unroll
    for (int a = 0; a < 2; a++)
#pragma unroll
        for (int b = 0; b < 6; b++)
#pragma unroll
            for (int c = 0; c < 4; c++) acc[a][b][c] = 0.0f;

    // prologue: W0 via cp.async, x0 via reg prefetch (fp32)
#pragma unroll
    for (int i = 0; i < 3; i++) {
        int slot = tid + 256*i; int n = slot >> 2; int c8 = (slot & 3) * 8;
        cpa16(s2u(&sm->wh[0][n*PK + c8]), g_wh + (size_t)n * C_ + c8);
        cpa16(s2u(&sm->wl[0][n*PK + c8]), g_wl + (size_t)n * C_ + c8);
    }
    CP_COMMIT();
    float4 xr[2];
#pragma unroll
    for (int i = 0; i < 2; i++) {
        int slot = tid + 256*i; int r = slot >> 3; int c = (slot & 7) * 4;
        xr[i] = *(const float4*)(x + (rowBase + r) * C_ + c);
    }

    for (int it = 0; it < 32; ++it) {
        const int s = it & 1;
        // split + store staged x into stage s
#pragma unroll
        for (int i = 0; i < 2; i++) {
            int slot = tid + 256*i; int r = slot >> 3; int c = (slot & 7) * 4;
            uint32_t h0, l0, h1, l1;
            split_pack(xr[i].x, xr[i].y, h0, l0);
            split_pack(xr[i].z, xr[i].w, h1, l1);
            uint2 ph = { h0, h1 }, pl = { l0, l1 };
            *reinterpret_cast<uint2*>(&sm->xh[s][r*PK + c]) = ph;
            *reinterpret_cast<uint2*>(&sm->xl[s][r*PK + c]) = pl;
        }
        // issue next W tile
        if (it < 31) {
            const int kt = (it + 1) * 32;
#pragma unroll
            for (int i = 0; i < 3; i++) {
                int slot = tid + 256*i; int n = slot >> 2; int c8 = (slot & 3) * 8;
                cpa16(s2u(&sm->wh[1-s][n*PK + c8]), g_wh + (size_t)n * C_ + kt + c8);
                cpa16(s2u(&sm->wl[1-s][n*PK + c8]), g_wl + (size_t)n * C_ + kt + c8);
            }
        }
        CP_COMMIT();
        CP_WAIT1();
        __syncthreads();

        // prefetch next x chunk (fp32, hidden under compute)
        if (it < 31) {
            const int kt = (it + 1) * 32;
#pragma unroll
            for (int i = 0; i < 2; i++) {
                int slot = tid + 256*i; int r = slot >> 3; int c = (slot & 7) * 4;
                xr[i] = *(const float4*)(x + (rowBase + r) * C_ + kt + c);
            }
        }

        const uint32_t* xhp = reinterpret_cast<const uint32_t*>(sm->xh[s]);
        const uint32_t* xlp = reinterpret_cast<const uint32_t*>(sm->xl[s]);
        const uint32_t* whp = reinterpret_cast<const uint32_t*>(sm->wh[s]);
        const uint32_t* wlp = reinterpret_cast<const uint32_t*>(sm->wl[s]);
#pragma unroll
        for (int ks = 0; ks < 2; ks++) {
            const int kw = tg + 8*ks;
            uint32_t ah[2][4], al[2][4];
#pragma unroll
            for (int mt = 0; mt < 2; mt++) {
                int r = m0 + 16*mt + g;
                ah[mt][0] = xhp[r*20 + kw];      ah[mt][1] = xhp[(r+8)*20 + kw];
                ah[mt][2] = xhp[r*20 + kw + 4];  ah[mt][3] = xhp[(r+8)*20 + kw + 4];
                al[mt][0] = xlp[r*20 + kw];      al[mt][1] = xlp[(r+8)*20 + kw];
                al[mt][2] = xlp[r*20 + kw + 4];  al[mt][3] = xlp[(r+8)*20 + kw + 4];
            }
#pragma unroll
            for (int nt = 0; nt < 6; nt++) {
                int n = n0 + 8*nt + g;
                uint32_t bh0 = whp[n*20 + kw], bh1 = whp[n*20 + kw + 4];
                uint32_t bl0 = wlp[n*20 + kw], bl1 = wlp[n*20 + kw + 4];
#pragma unroll
                for (int mt = 0; mt < 2; mt++) {
                    mma_bf16(acc[mt][nt], ah[mt], bh0, bh1);
                    mma_bf16(acc[mt][nt], ah[mt], bl0, bl1);
                    mma_bf16(acc[mt][nt], al[mt], bh0, bh1);
                }
            }
        }
        __syncthreads();
    }

    const float qscale = 0.03125f;   // C^-0.5
#pragma unroll
    for (int mt = 0; mt < 2; mt++) {
#pragma unroll
        for (int nt = 0; nt < 6; nt++) {
            int gc = n0 + 8*nt;
            float* c = acc[mt][nt];
            int r0 = m0 + 16*mt + g;
            size_t row0 = rowBase + r0, row1 = row0 + 8;
            if (gc < 64) {
                int col = gc + 2*tg;
                uint32_t h, l;
                split_pack(c[0]*qscale, c[1]*qscale, h, l);
                *reinterpret_cast<uint32_t*>(&g_qh[row0*H_ + col]) = h;
                *reinterpret_cast<uint32_t*>(&g_ql[row0*H_ + col]) = l;
                split_pack(c[2]*qscale, c[3]*qscale, h, l);
                *reinterpret_cast<uint32_t*>(&g_qh[row1*H_ + col]) = h;
                *reinterpret_cast<uint32_t*>(&g_ql[row1*H_ + col]) = l;
            } else if (gc < 128) {
                int col = gc - 64 + 2*tg;
                uint32_t h, l;
                split_pack(c[0], c[1], h, l);
                *reinterpret_cast<uint32_t*>(&g_kh[row0*H_ + col]) = h;
                *reinterpret_cast<uint32_t*>(&g_kl[row0*H_ + col]) = l;
                split_pack(c[2], c[3], h, l);
                *reinterpret_cast<uint32_t*>(&g_kh[row1*H_ + col]) = h;
                *reinterpret_cast<uint32_t*>(&g_kl[row1*H_ + col]) = l;
            } else {
                int h0 = gc - 128 + 2*tg;
                size_t bb = rowBase >> 11;
                size_t tb = (rowBase & 2047);
                __nv_bfloat16 hh, ll;
                split1(c[0], hh, ll);
                g_vh[(bb*H_ + h0    )*T_ + tb + r0] = hh;
                g_vl[(bb*H_ + h0    )*T_ + tb + r0] = ll;
                split1(c[1], hh, ll);
                g_vh[(bb*H_ + h0 + 1)*T_ + tb + r0] = hh;
                g_vl[(bb*H_ + h0 + 1)*T_ + tb + r0] = ll;
                split1(c[2], hh, ll);
                g_vh[(bb*H_ + h0    )*T_ + tb + r0 + 8] = hh;
                g_vl[(bb*H_ + h0    )*T_ + tb + r0 + 8] = ll;
                split1(c[3], hh, ll);
                g_vh[(bb*H_ + h0 + 1)*T_ + tb + r0 + 8] = hh;
                g_vl[(bb*H_ + h0 + 1)*T_ + tb + r0 + 8] = ll;
            }
        }
    }
}

// ---------------------------------------------------------------------------
// Kernel 2: causal flash attention, bf16x3 mma, cp.async double-buffered K/V.
// ---------------------------------------------------------------------------
struct FaS {
    __nv_bfloat16 qh[64*PT], ql[64*PT];
    __nv_bfloat16 kh[2][64*PT], kl[2][64*PT];
    __nv_bfloat16 vh[2][64*PT], vl[2][64*PT];
};

__global__ __launch_bounds__(128, 1) void flash_mma(float* __restrict__ out)
{
    extern __shared__ char smraw[];
    FaS* sm = reinterpret_cast<FaS*>(smraw);
    const int tid = threadIdx.x, lane = tid & 31;
    const int g = lane >> 2, tg = lane & 3;
    const int m0 = 16 * (tid >> 5);
    const int blk = blockIdx.x;
    const int qt = 31 - (blk >> 3);   // heavy tiles first
    const int b  = blk & 7;

    const __nv_bfloat16* khb = g_kh + (size_t)b*T_*H_;
    const __nv_bfloat16* klb = g_kl + (size_t)b*T_*H_;
    const __nv_bfloat16* vhb = g_vh + (size_t)b*H_*T_;
    const __nv_bfloat16* vlb = g_vl + (size_t)b*H_*T_;

    // prologue group 0: Q + KV tile 0
    {
        const __nv_bfloat16* sh = g_qh + (size_t)(b*T_ + qt*64) * H_;
        const __nv_bfloat16* sl = g_ql + (size_t)(b*T_ + qt*64) * H_;
#pragma unroll
        for (int i = 0; i < 4; i++) {
            int slot = tid + 128*i; int r = slot >> 3; int c = (slot & 7) * 8;
            cpa16(s2u(&sm->qh[r*PT + c]), sh + r*H_ + c);
            cpa16(s2u(&sm->ql[r*PT + c]), sl + r*H_ + c);
            cpa16(s2u(&sm->kh[0][r*PT + c]), khb + (size_t)r*H_ + c);
            cpa16(s2u(&sm->kl[0][r*PT + c]), klb + (size_t)r*H_ + c);
            cpa16(s2u(&sm->vh[0][r*PT + c]), vhb + (size_t)r*T_ + c);
            cpa16(s2u(&sm->vl[0][r*PT + c]), vlb + (size_t)r*T_ + c);
        }
        CP_COMMIT();
    }

    float O[8][4];
#pragma unroll
    for (int a = 0; a < 8; a++)
#pragma unroll
        for (int c = 0; c < 4; c++) O[a][c] = 0.0f;
    float mr[2] = { -1e30f, -1e30f }, lr[2] = { 0.0f, 0.0f };

    for (int kvt = 0; kvt <= qt; ++kvt) {
        const int s = kvt & 1;
        __syncthreads();   // WAR: all warps done reading stage 1-s
        if (kvt < qt) {
            const int nt4 = (kvt + 1) * 64;
#pragma unroll
            for (int i = 0; i < 4; i++) {
                int slot = tid + 128*i; int r = slot >> 3; int c = (slot & 7) * 8;
                cpa16(s2u(&sm->kh[1-s][r*PT + c]), khb + (size_t)(nt4 + r)*H_ + c);
                cpa16(s2u(&sm->kl[1-s][r*PT + c]), klb + (size_t)(nt4 + r)*H_ + c);
                cpa16(s2u(&sm->vh[1-s][r*PT + c]), vhb + (size_t)r*T_ + nt4 + c);
                cpa16(s2u(&sm->vl[1-s][r*PT + c]), vlb + (size_t)r*T_ + nt4 + c);
            }
        }
        CP_COMMIT();
        CP_WAIT1();        // everything except latest group done => stage s ready
        __syncthreads();

        float Sf[8][4];
#pragma unroll
        for (int a = 0; a < 8; a++)
#pragma unroll
            for (int c = 0; c < 4; c++) Sf[a][c] = 0.0f;

        const uint32_t* qhp = reinterpret_cast<const uint32_t*>(sm->qh);
        const uint32_t* qlp = reinterpret_cast<const uint32_t*>(sm->ql);
        const uint32_t* khp = reinterpret_cast<const uint32_t*>(sm->kh[s]);
        const uint32_t* klp = reinterpret_cast<const uint32_t*>(sm->kl[s]);
#pragma unroll
        for (int ks = 0; ks < 4; ks++) {
            const int kw = tg + 8*ks;
            uint32_t ah[4], al[4];
            int r = m0 + g;
            ah[0] = qhp[r*36 + kw];       ah[1] = qhp[(r+8)*36 + kw];
            ah[2] = qhp[r*36 + kw + 4];   ah[3] = qhp[(r+8)*36 + kw + 4];
            al[0] = qlp[r*36 + kw];       al[1] = qlp[(r+8)*36 + kw];
            al[2] = qlp[r*36 + kw + 4];   al[3] = qlp[(r+8)*36 + kw + 4];
#pragma unroll
            for (int nt = 0; nt < 8; nt++) {
                int n = 8*nt + g;
                uint32_t bh0 = khp[n*36 + kw], bh1 = khp[n*36 + kw + 4];
                uint32_t bl0 = klp[n*36 + kw], bl1 = klp[n*36 + kw + 4];
                mma_bf16(Sf[nt], ah, bh0, bh1);
                mma_bf16(Sf[nt], ah, bl0, bl1);
                mma_bf16(Sf[nt], al, bh0, bh1);
            }
        }

        if (kvt == qt) {
#pragma unroll
            for (int nt = 0; nt < 8; nt++) {
                int colb = 8*nt + 2*tg;
                int row0 = m0 + g, row1 = row0 + 8;
                if (colb     > row0) Sf[nt][0] = -1e30f;
                if (colb + 1 > row0) Sf[nt][1] = -1e30f;
                if (colb     > row1) Sf[nt][2] = -1e30f;
                if (colb + 1 > row1) Sf[nt][3] = -1e30f;
            }
        }

#pragma unroll
        for (int rr = 0; rr < 2; rr++) {
            float mx = -1e30f;
#pragma unroll
            for (int nt = 0; nt < 8; nt++)
                mx = fmaxf(mx, fmaxf(Sf[nt][2*rr], Sf[nt][2*rr+1]));
            mx = fmaxf(mx, __shfl_xor_sync(0xffffffffu, mx, 1));
            mx = fmaxf(mx, __shfl_xor_sync(0xffffffffu, mx, 2));
            float mn = fmaxf(mr[rr], mx);
            float corr = __expf(mr[rr] - mn);
            mr[rr] = mn;
            float sum = 0.0f;
#pragma unroll
            for (int nt = 0; nt < 8; nt++) {
                float p0 = __expf(Sf[nt][2*rr]   - mn);
                float p1 = __expf(Sf[nt][2*rr+1] - mn);
                Sf[nt][2*rr] = p0; Sf[nt][2*rr+1] = p1;
                sum += p0 + p1;
            }
            sum += __shfl_xor_sync(0xffffffffu, sum, 1);
            sum += __shfl_xor_sync(0xffffffffu, sum, 2);
            lr[rr] = lr[rr]*corr + sum;
#pragma unroll
            for (int nt = 0; nt < 8; nt++) {
                O[nt][2*rr]   *= corr;
                O[nt][2*rr+1] *= corr;
            }
        }

        const uint32_t* vhp = reinterpret_cast<const uint32_t*>(sm->vh[s]);
        const uint32_t* vlp = reinterpret_cast<const uint32_t*>(sm->vl[s]);
#pragma unroll
        for (int ks = 0; ks < 4; ks++) {
            uint32_t ph[4], pl[4];
            split_pack(Sf[2*ks][0],   Sf[2*ks][1],   ph[0], pl[0]);
            split_pack(Sf[2*ks][2],   Sf[2*ks][3],   ph[1], pl[1]);
            split_pack(Sf[2*ks+1][0], Sf[2*ks+1][1], ph[2], pl[2]);
            split_pack(Sf[2*ks+1][2], Sf[2*ks+1][3], ph[3], pl[3]);
            const int kw = tg + 8*ks;
#pragma unroll
            for (int nt = 0; nt < 8; nt++) {
                int n = 8*nt + g;
                uint32_t bh0 = vhp[n*36 + kw], bh1 = vhp[n*36 + kw + 4];
                uint32_t bl0 = vlp[n*36 + kw], bl1 = vlp[n*36 + kw + 4];
                mma_bf16(O[nt], ph, bh0, bh1);
                mma_bf16(O[nt], ph, bl0, bl1);
                mma_bf16(O[nt], pl, bh0, bh1);
            }
        }
    }

    float inv0 = 1.0f / lr[0], inv1 = 1.0f / lr[1];
    size_t row0 = (size_t)b*T_ + (size_t)qt*64 + m0 + g;
    size_t row1 = row0 + 8;
#pragma unroll
    for (int nt = 0; nt < 8; nt++) {
        int col = 8*nt + 2*tg;
        float2 v0 = { O[nt][0]*inv0, O[nt][1]*inv0 };
        float2 v1 = { O[nt][2]*inv1, O[nt][3]*inv1 };
        *reinterpret_cast<float2*>(out + row0*H_ + col) = v0;
        *reinterpret_cast<float2*>(out + row1*H_ + col) = v1;
    }
}

// ---------------------------------------------------------------------------
extern "C" void kernel_launch(void* const* d_in, const int* in_sizes, int n_in,
                              void* d_out, int out_size)
{
    const float* x  = (const float*)d_in[0];
    const float* Wk = (const float*)d_in[1];
    const float* Wq = (const float*)d_in[2];
    const float* Wv = (const float*)d_in[3];
    float* out = (float*)d_out;

    wconv<<<192, 256>>>(Wk, Wq, Wv);

    const int psm = (int)sizeof(ProjS);   // 81920
    cudaFuncSetAttribute(qkv_proj, cudaFuncAttributeMaxDynamicSharedMemorySize, psm);
    qkv_proj<<<NROW / 64, 256, psm>>>(x);

    const int fsm = (int)sizeof(FaS);     // 92160
    cudaFuncSetAttribute(flash_mma, cudaFuncAttributeMaxDynamicSharedMemorySize, fsm);
    flash_mma<<<(T_/64) * B_, 128, fsm>>>(out);
}

// round 6
// speedup vs baseline: 4.5502x; 1.1644x over previous
#include <cuda_runtime.h>
#include <cuda_bf16.h>
#include <cstdint>

#define B_ 8
#define T_ 2048
#define C_ 1024
#define H_ 64
#define NROW (B_*T_)
#define PK 40   // proj smem k-stride (bf16)
#define PT 72   // flash smem stride (bf16)

// pre-split W (tiny); q/k/v outputs bf16 hi/lo
__device__ __nv_bfloat16 g_wh[192*C_];   // [n][k]
__device__ __nv_bfloat16 g_wl[192*C_];
__device__ __nv_bfloat16 g_qh[NROW*H_];
__device__ __nv_bfloat16 g_ql[NROW*H_];
__device__ __nv_bfloat16 g_kh[NROW*H_];
__device__ __nv_bfloat16 g_kl[NROW*H_];
__device__ __nv_bfloat16 g_vh[B_*H_*T_];   // [b][h][t]
__device__ __nv_bfloat16 g_vl[B_*H_*T_];

// split-KV partials
__device__ float g_Om[2][NROW*H_];
__device__ float g_m[2][NROW];
__device__ float g_l[2][NROW];

// ---------------------------------------------------------------------------
__device__ __forceinline__ void mma_bf16(float* c, const uint32_t* a,
                                         uint32_t b0, uint32_t b1) {
    asm volatile("mma.sync.aligned.m16n8k16.row.col.f32.bf16.bf16.f32 "
        "{%0,%1,%2,%3}, {%4,%5,%6,%7}, {%8,%9}, {%0,%1,%2,%3};"
        : "+f"(c[0]), "+f"(c[1]), "+f"(c[2]), "+f"(c[3])
        : "r"(a[0]), "r"(a[1]), "r"(a[2]), "r"(a[3]), "r"(b0), "r"(b1));
}
__device__ __forceinline__ void split1(float v, __nv_bfloat16& h, __nv_bfloat16& l) {
    h = __float2bfloat16_rn(v);
    l = __float2bfloat16_rn(v - __bfloat162float(h));
}
__device__ __forceinline__ uint32_t packb(__nv_bfloat16 e0, __nv_bfloat16 e1) {
    return (uint32_t)__bfloat16_as_ushort(e0) |
           ((uint32_t)__bfloat16_as_ushort(e1) << 16);
}
__device__ __forceinline__ void split_pack(float a, float b, uint32_t& hi, uint32_t& lo) {
    __nv_bfloat16 ah, al, bh, bl;
    split1(a, ah, al); split1(b, bh, bl);
    hi = packb(ah, bh); lo = packb(al, bl);
}
__device__ __forceinline__ uint32_t s2u(const void* p) {
    uint32_t a;
    asm("{ .reg .u64 t; cvta.to.shared.u64 t, %1; cvt.u32.u64 %0, t; }" : "=r"(a) : "l"(p));
    return a;
}
__device__ __forceinline__ void cpa16(uint32_t dst, const void* src) {
    asm volatile("cp.async.cg.shared.global [%0], [%1], 16;" :: "r"(dst), "l"(src) : "memory");
}
#define CP_COMMIT() asm volatile("cp.async.commit_group;" ::: "memory")
#define CP_WAIT1()  asm volatile("cp.async.wait_group 1;" ::: "memory")
#define CP_WAIT0()  asm volatile("cp.async.wait_group 0;" ::: "memory")

// ---------------------------------------------------------------------------
// Kernel 0: split W into bf16 hi/lo, transposed to [n][k].
// ---------------------------------------------------------------------------
__global__ void wconv(const float* __restrict__ Wk, const float* __restrict__ Wq,
                      const float* __restrict__ Wv)
{
    int slot = blockIdx.x * 256 + threadIdx.x;
    int k  = slot >> 4;
    int nq = (slot & 15) * 4;
    int mat = k >> 10;
    int kk = k & 1023;
    const float* W = (mat == 0) ? Wq : ((mat == 1) ? Wk : Wv);
    float4 v = *(const float4*)(W + (size_t)kk * H_ + nq);
    float f[4] = { v.x, v.y, v.z, v.w };
#pragma unroll
    for (int j = 0; j < 4; j++) {
        __nv_bfloat16 h, l; split1(f[j], h, l);
        size_t o = (size_t)(mat * 64 + nq + j) * C_ + kk;
        g_wh[o] = h; g_wl[o] = l;
    }
}

// ---------------------------------------------------------------------------
// Kernel 1: QKV projection (unchanged from R5 — known good).
// ---------------------------------------------------------------------------
struct ProjS {
    __nv_bfloat16 xh[2][64*PK];
    __nv_bfloat16 xl[2][64*PK];
    __nv_bfloat16 wh[2][192*PK];
    __nv_bfloat16 wl[2][192*PK];
};

__global__ __launch_bounds__(256, 2) void qkv_proj(const float* __restrict__ x)
{
    extern __shared__ char smraw[];
    ProjS* sm = reinterpret_cast<ProjS*>(smraw);
    const int tid = threadIdx.x, lane = tid & 31, wid = tid >> 5;
    const int g = lane >> 2, tg = lane & 3;
    const int m0 = 32 * (wid >> 2);
    const int n0 = 48 * (wid & 3);
    const size_t rowBase = (size_t)blockIdx.x * 64;

    float acc[2][6][4];
#pragma unroll
    for (int a = 0; a < 2; a++)
#pragma unroll
        for (int b = 0; b < 6; b++)
#pragma unroll
            for (int c = 0; c < 4; c++) acc[a][b][c] = 0.0f;

#pragma unroll
    for (int i = 0; i < 3; i++) {
        int slot = tid + 256*i; int n = slot >> 2; int c8 = (slot & 3) * 8;
        cpa16(s2u(&sm->wh[0][n*PK + c8]), g_wh + (size_t)n * C_ + c8);
        cpa16(s2u(&sm->wl[0][n*PK + c8]), g_wl + (size_t)n * C_ + c8);
    }
    CP_COMMIT();
    float4 xr[2];
#pragma unroll
    for (int i = 0; i < 2; i++) {
        int slot = tid + 256*i; int r = slot >> 3; int c = (slot & 7) * 4;
        xr[i] = *(const float4*)(x + (rowBase + r) * C_ + c);
    }

    for (int it = 0; it < 32; ++it) {
        const int s = it & 1;
#pragma unroll
        for (int i = 0; i < 2; i++) {
            int slot = tid + 256*i; int r = slot >> 3; int c = (slot & 7) * 4;
            uint32_t h0, l0, h1, l1;
            split_pack(xr[i].x, xr[i].y, h0, l0);
            split_pack(xr[i].z, xr[i].w, h1, l1);
            uint2 ph = { h0, h1 }, pl = { l0, l1 };
            *reinterpret_cast<uint2*>(&sm->xh[s][r*PK + c]) = ph;
            *reinterpret_cast<uint2*>(&sm->xl[s][r*PK + c]) = pl;
        }
        if (it < 31) {
            const int kt = (it + 1) * 32;
#pragma unroll
            for (int i = 0; i < 3; i++) {
                int slot = tid + 256*i; int n = slot >> 2; int c8 = (slot & 3) * 8;
                cpa16(s2u(&sm->wh[1-s][n*PK + c8]), g_wh + (size_t)n * C_ + kt + c8);
                cpa16(s2u(&sm->wl[1-s][n*PK + c8]), g_wl + (size_t)n * C_ + kt + c8);
            }
        }
        CP_COMMIT();
        CP_WAIT1();
        __syncthreads();

        if (it < 31) {
            const int kt = (it + 1) * 32;
#pragma unroll
            for (int i = 0; i < 2; i++) {
                int slot = tid + 256*i; int r = slot >> 3; int c = (slot & 7) * 4;
                xr[i] = *(const float4*)(x + (rowBase + r) * C_ + kt + c);
            }
        }

        const uint32_t* xhp = reinterpret_cast<const uint32_t*>(sm->xh[s]);
        const uint32_t* xlp = reinterpret_cast<const uint32_t*>(sm->xl[s]);
        const uint32_t* whp = reinterpret_cast<const uint32_t*>(sm->wh[s]);
        const uint32_t* wlp = reinterpret_cast<const uint32_t*>(sm->wl[s]);
#pragma unroll
        for (int ks = 0; ks < 2; ks++) {
            const int kw = tg + 8*ks;
            uint32_t ah[2][4], al[2][4];
#pragma unroll
            for (int mt = 0; mt < 2; mt++) {
                int r = m0 + 16*mt + g;
                ah[mt][0] = xhp[r*20 + kw];      ah[mt][1] = xhp[(r+8)*20 + kw];
                ah[mt][2] = xhp[r*20 + kw + 4];  ah[mt][3] = xhp[(r+8)*20 + kw + 4];
                al[mt][0] = xlp[r*20 + kw];      al[mt][1] = xlp[(r+8)*20 + kw];
                al[mt][2] = xlp[r*20 + kw + 4];  al[mt][3] = xlp[(r+8)*20 + kw + 4];
            }
#pragma unroll
            for (int nt = 0; nt < 6; nt++) {
                int n = n0 + 8*nt + g;
                uint32_t bh0 = whp[n*20 + kw], bh1 = whp[n*20 + kw + 4];
                uint32_t bl0 = wlp[n*20 + kw], bl1 = wlp[n*20 + kw + 4];
#pragma unroll
                for (int mt = 0; mt < 2; mt++) {
                    mma_bf16(acc[mt][nt], ah[mt], bh0, bh1);
                    mma_bf16(acc[mt][nt], ah[mt], bl0, bl1);
                    mma_bf16(acc[mt][nt], al[mt], bh0, bh1);
                }
            }
        }
        __syncthreads();
    }

    const float qscale = 0.03125f;
#pragma unroll
    for (int mt = 0; mt < 2; mt++) {
#pragma unroll
        for (int nt = 0; nt < 6; nt++) {
            int gc = n0 + 8*nt;
            float* c = acc[mt][nt];
            int r0 = m0 + 16*mt + g;
            size_t row0 = rowBase + r0, row1 = row0 + 8;
            if (gc < 64) {
                int col = gc + 2*tg;
                uint32_t h, l;
                split_pack(c[0]*qscale, c[1]*qscale, h, l);
                *reinterpret_cast<uint32_t*>(&g_qh[row0*H_ + col]) = h;
                *reinterpret_cast<uint32_t*>(&g_ql[row0*H_ + col]) = l;
                split_pack(c[2]*qscale, c[3]*qscale, h, l);
                *reinterpret_cast<uint32_t*>(&g_qh[row1*H_ + col]) = h;
                *reinterpret_cast<uint32_t*>(&g_ql[row1*H_ + col]) = l;
            } else if (gc < 128) {
                int col = gc - 64 + 2*tg;
                uint32_t h, l;
                split_pack(c[0], c[1], h, l);
                *reinterpret_cast<uint32_t*>(&g_kh[row0*H_ + col]) = h;
                *reinterpret_cast<uint32_t*>(&g_kl[row0*H_ + col]) = l;
                split_pack(c[2], c[3], h, l);
                *reinterpret_cast<uint32_t*>(&g_kh[row1*H_ + col]) = h;
                *reinterpret_cast<uint32_t*>(&g_kl[row1*H_ + col]) = l;
            } else {
                int h0 = gc - 128 + 2*tg;
                size_t bb = rowBase >> 11;
                size_t tb = (rowBase & 2047);
                __nv_bfloat16 hh, ll;
                split1(c[0], hh, ll);
                g_vh[(bb*H_ + h0    )*T_ + tb + r0] = hh;
                g_vl[(bb*H_ + h0    )*T_ + tb + r0] = ll;
                split1(c[1], hh, ll);
                g_vh[(bb*H_ + h0 + 1)*T_ + tb + r0] = hh;
                g_vl[(bb*H_ + h0 + 1)*T_ + tb + r0] = ll;
                split1(c[2], hh, ll);
                g_vh[(bb*H_ + h0    )*T_ + tb + r0 + 8] = hh;
                g_vl[(bb*H_ + h0    )*T_ + tb + r0 + 8] = ll;
                split1(c[3], hh, ll);
                g_vh[(bb*H_ + h0 + 1)*T_ + tb + r0 + 8] = hh;
                g_vl[(bb*H_ + h0 + 1)*T_ + tb + r0 + 8] = ll;
            }
        }
    }
}

// ---------------------------------------------------------------------------
// Kernel 2: split-KV causal flash attention. Each CTA: one (b, qt, parity h);
// processes kv tiles kvt = h, h+2, ... <= qt. Writes unnormalized partial
// (O, m, l) to scratch. Grid 512.
// ---------------------------------------------------------------------------
struct FaS {
    __nv_bfloat16 qh[64*PT], ql[64*PT];
    __nv_bfloat16 kh[2][64*PT], kl[2][64*PT];
    __nv_bfloat16 vh[2][64*PT], vl[2][64*PT];
};

__global__ __launch_bounds__(128) void flash_mma()
{
    extern __shared__ char smraw[];
    FaS* sm = reinterpret_cast<FaS*>(smraw);
    const int tid = threadIdx.x, lane = tid & 31;
    const int g = lane >> 2, tg = lane & 3;
    const int m0 = 16 * (tid >> 5);
    const int blk = blockIdx.x;
    const int h    = blk & 1;
    const int rest = blk >> 1;
    const int qt = 31 - (rest >> 3);   // heavy tiles first
    const int b  = rest & 7;
    const int ntiles = (qt >= h) ? ((qt - h) >> 1) + 1 : 0;

    const __nv_bfloat16* khb = g_kh + (size_t)b*T_*H_;
    const __nv_bfloat16* klb = g_kl + (size_t)b*T_*H_;
    const __nv_bfloat16* vhb = g_vh + (size_t)b*H_*T_;
    const __nv_bfloat16* vlb = g_vl + (size_t)b*H_*T_;

    // prologue: Q (+ first KV tile if any)
    {
        const __nv_bfloat16* sh = g_qh + (size_t)(b*T_ + qt*64) * H_;
        const __nv_bfloat16* sl = g_ql + (size_t)(b*T_ + qt*64) * H_;
        const int t0 = h * 64;
#pragma unroll
        for (int i = 0; i < 4; i++) {
            int slot = tid + 128*i; int r = slot >> 3; int c = (slot & 7) * 8;
            cpa16(s2u(&sm->qh[r*PT + c]), sh + r*H_ + c);
            cpa16(s2u(&sm->ql[r*PT + c]), sl + r*H_ + c);
            if (ntiles > 0) {
                cpa16(s2u(&sm->kh[0][r*PT + c]), khb + (size_t)(t0 + r)*H_ + c);
                cpa16(s2u(&sm->kl[0][r*PT + c]), klb + (size_t)(t0 + r)*H_ + c);
                cpa16(s2u(&sm->vh[0][r*PT + c]), vhb + (size_t)r*T_ + t0 + c);
                cpa16(s2u(&sm->vl[0][r*PT + c]), vlb + (size_t)r*T_ + t0 + c);
            }
        }
        CP_COMMIT();
    }

    float O[8][4];
#pragma unroll
    for (int a = 0; a < 8; a++)
#pragma unroll
        for (int c = 0; c < 4; c++) O[a][c] = 0.0f;
    float mr[2] = { -1e30f, -1e30f }, lr[2] = { 0.0f, 0.0f };

    for (int i = 0; i < ntiles; ++i) {
        const int kvt = h + 2*i;
        const int s = i & 1;
        __syncthreads();
        if (i + 1 < ntiles) {
            const int nt4 = (kvt + 2) * 64;
#pragma unroll
            for (int j = 0; j < 4; j++) {
                int slot = tid + 128*j; int r = slot >> 3; int c = (slot & 7) * 8;
                cpa16(s2u(&sm->kh[1-s][r*PT + c]), khb + (size_t)(nt4 + r)*H_ + c);
                cpa16(s2u(&sm->kl[1-s][r*PT + c]), klb + (size_t)(nt4 + r)*H_ + c);
                cpa16(s2u(&sm->vh[1-s][r*PT + c]), vhb + (size_t)r*T_ + nt4 + c);
                cpa16(s2u(&sm->vl[1-s][r*PT + c]), vlb + (size_t)r*T_ + nt4 + c);
            }
        }
        CP_COMMIT();
        CP_WAIT1();
        __syncthreads();

        float Sf[8][4];
#pragma unroll
        for (int a = 0; a < 8; a++)
#pragma unroll
            for (int c = 0; c < 4; c++) Sf[a][c] = 0.0f;

        const uint32_t* qhp = reinterpret_cast<const uint32_t*>(sm->qh);
        const uint32_t* qlp = reinterpret_cast<const uint32_t*>(sm->ql);
        const uint32_t* khp = reinterpret_cast<const uint32_t*>(sm->kh[s]);
        const uint32_t* klp = reinterpret_cast<const uint32_t*>(sm->kl[s]);
#pragma unroll
        for (int ks = 0; ks < 4; ks++) {
            const int kw = tg + 8*ks;
            uint32_t ah[4], al[4];
            int r = m0 + g;
            ah[0] = qhp[r*36 + kw];       ah[1] = qhp[(r+8)*36 + kw];
            ah[2] = qhp[r*36 + kw + 4];   ah[3] = qhp[(r+8)*36 + kw + 4];
            al[0] = qlp[r*36 + kw];       al[1] = qlp[(r+8)*36 + kw];
            al[2] = qlp[r*36 + kw + 4];   al[3] = qlp[(r+8)*36 + kw + 4];
#pragma unroll
            for (int nt = 0; nt < 8; nt++) {
                int n = 8*nt + g;
                uint32_t bh0 = khp[n*36 + kw], bh1 = khp[n*36 + kw + 4];
                uint32_t bl0 = klp[n*36 + kw], bl1 = klp[n*36 + kw + 4];
                mma_bf16(Sf[nt], ah, bh0, bh1);
                mma_bf16(Sf[nt], ah, bl0, bl1);
                mma_bf16(Sf[nt], al, bh0, bh1);
            }
        }

        if (kvt == qt) {
#pragma unroll
            for (int nt = 0; nt < 8; nt++) {
                int colb = 8*nt + 2*tg;
                int row0 = m0 + g, row1 = row0 + 8;
                if (colb     > row0) Sf[nt][0] = -1e30f;
                if (colb + 1 > row0) Sf[nt][1] = -1e30f;
                if (colb     > row1) Sf[nt][2] = -1e30f;
                if (colb + 1 > row1) Sf[nt][3] = -1e30f;
            }
        }

#pragma unroll
        for (int rr = 0; rr < 2; rr++) {
            float mx = -1e30f;
#pragma unroll
            for (int nt = 0; nt < 8; nt++)
                mx = fmaxf(mx, fmaxf(Sf[nt][2*rr], Sf[nt][2*rr+1]));
            mx = fmaxf(mx, __shfl_xor_sync(0xffffffffu, mx, 1));
            mx = fmaxf(mx, __shfl_xor_sync(0xffffffffu, mx, 2));
            float mn = fmaxf(mr[rr], mx);
            float corr = __expf(mr[rr] - mn);
            mr[rr] = mn;
            float sum = 0.0f;
#pragma unroll
            for (int nt = 0; nt < 8; nt++) {
                float p0 = __expf(Sf[nt][2*rr]   - mn);
                float p1 = __expf(Sf[nt][2*rr+1] - mn);
                Sf[nt][2*rr] = p0; Sf[nt][2*rr+1] = p1;
                sum += p0 + p1;
            }
            sum += __shfl_xor_sync(0xffffffffu, sum, 1);
            sum += __shfl_xor_sync(0xffffffffu, sum, 2);
            lr[rr] = lr[rr]*corr + sum;
#pragma unroll
            for (int nt = 0; nt < 8; nt++) {
                O[nt][2*rr]   *= corr;
                O[nt][2*rr+1] *= corr;
            }
        }

        const uint32_t* vhp = reinterpret_cast<const uint32_t*>(sm->vh[s]);
        const uint32_t* vlp = reinterpret_cast<const uint32_t*>(sm->vl[s]);
#pragma unroll
        for (int ks = 0; ks < 4; ks++) {
            uint32_t ph[4], pl[4];
            split_pack(Sf[2*ks][0],   Sf[2*ks][1],   ph[0], pl[0]);
            split_pack(Sf[2*ks][2],   Sf[2*ks][3],   ph[1], pl[1]);
            split_pack(Sf[2*ks+1][0], Sf[2*ks+1][1], ph[2], pl[2]);
            split_pack(Sf[2*ks+1][2], Sf[2*ks+1][3], ph[3], pl[3]);
            const int kw = tg + 8*ks;
#pragma unroll
            for (int nt = 0; nt < 8; nt++) {
                int n = 8*nt + g;
                uint32_t bh0 = vhp[n*36 + kw], bh1 = vhp[n*36 + kw + 4];
                uint32_t bl0 = vlp[n*36 + kw], bl1 = vlp[n*36 + kw + 4];
                mma_bf16(O[nt], ph, bh0, bh1);
                mma_bf16(O[nt], ph, bl0, bl1);
                mma_bf16(O[nt], pl, bh0, bh1);
            }
        }
    }

    CP_WAIT0();

    // epilogue: write unnormalized partial O + (m, l)
    size_t row0 = (size_t)b*T_ + (size_t)qt*64 + m0 + g;
    size_t row1 = row0 + 8;
    float* Od = g_Om[h];
#pragma unroll
    for (int nt = 0; nt < 8; nt++) {
        int col = 8*nt + 2*tg;
        float2 v0 = { O[nt][0], O[nt][1] };
        float2 v1 = { O[nt][2], O[nt][3] };
        *reinterpret_cast<float2*>(Od + row0*H_ + col) = v0;
        *reinterpret_cast<float2*>(Od + row1*H_ + col) = v1;
    }
    if (tg == 0) {
        g_m[h][row0] = mr[0]; g_l[h][row0] = lr[0];
        g_m[h][row1] = mr[1]; g_l[h][row1] = lr[1];
    }
}

// ---------------------------------------------------------------------------
// Kernel 3: merge the two split-KV partials.
// ---------------------------------------------------------------------------
__global__ __launch_bounds__(256) void fa_merge(float* __restrict__ out)
{
    int idx = blockIdx.x * 256 + threadIdx.x;      // float4 slots: NROW*H_/4
    int row = idx >> 4;
    int c4  = (idx & 15) * 4;
    float m0v = g_m[0][row], m1v = g_m[1][row];
    float l0v = g_l[0][row], l1v = g_l[1][row];
    float M = fmaxf(m0v, m1v);
    float a0 = __expf(m0v - M), a1 = __expf(m1v - M);
    float denom = l0v * a0 + l1v * a1;
    float inv = 1.0f / denom;
    float4 o0 = *reinterpret_cast<const float4*>(&g_Om[0][(size_t)row*H_ + c4]);
    float4 o1 = *reinterpret_cast<const float4*>(&g_Om[1][(size_t)row*H_ + c4]);
    float4 r;
    r.x = (o0.x*a0 + o1.x*a1) * inv;
    r.y = (o0.y*a0 + o1.y*a1) * inv;
    r.z = (o0.z*a0 + o1.z*a1) * inv;
    r.w = (o0.w*a0 + o1.w*a1) * inv;
    *reinterpret_cast<float4*>(out + (size_t)row*H_ + c4) = r;
}

// ---------------------------------------------------------------------------
extern "C" void kernel_launch(void* const* d_in, const int* in_sizes, int n_in,
                              void* d_out, int out_size)
{
    const float* x  = (const float*)d_in[0];
    const float* Wk = (const float*)d_in[1];
    const float* Wq = (const float*)d_in[2];
    const float* Wv = (const float*)d_in[3];
    float* out = (float*)d_out;

    wconv<<<192, 256>>>(Wk, Wq, Wv);

    const int psm = (int)sizeof(ProjS);   // 81920
    cudaFuncSetAttribute(qkv_proj, cudaFuncAttributeMaxDynamicSharedMemorySize, psm);
    qkv_proj<<<NROW / 64, 256, psm>>>(x);

    const int fsm = (int)sizeof(FaS);     // 92160
    cudaFuncSetAttribute(flash_mma, cudaFuncAttributeMaxDynamicSharedMemorySize, fsm);
    flash_mma<<<(T_/64) * B_ * 2, 128, fsm>>>();

    fa_merge<<<NROW * H_ / 4 / 256, 256>>>(out);
}